// round 1
// baseline (speedup 1.0000x reference)
#include <cuda_runtime.h>
#include <math.h>

// Problem constants (fixed shapes)
#define Nn   100000
#define Ecnt 1600000
#define ET   (Ecnt + Nn)      // edges + self loops = 1,700,000
#define INCH 128
#define HEADS 4
#define HID   32
#define OUTCH 64

// ---------------- scratch (device globals; no allocation allowed) ----------------
__device__ float4 g_xp[Nn * 32];      // xp [N,128] for conv1 / xp2 [N,64] for conv2
__device__ float4 g_h[Nn * 64];       // h = relu(concat(h_ppi, h_go)) [N,256]
__device__ float  g_asrc[Nn * 4];     // per-node attention src terms (4 heads / 1 head)
__device__ float  g_adst[Nn * 4];
__device__ int    g_deg[Nn];
__device__ int    g_cursor[Nn];
__device__ int    g_rowstart[Nn + 1];
__device__ int    g_csr[ET];          // src node per CSR slot (grouped by dst)

// ---------------- CSR build ----------------
__global__ void k_zero_counts() {
    int i = blockIdx.x * blockDim.x + threadIdx.x;
    if (i < Nn) { g_deg[i] = 0; g_cursor[i] = 0; }
}

__global__ void k_degree(const int* __restrict__ ei) {
    int e = blockIdx.x * blockDim.x + threadIdx.x;
    if (e >= ET) return;
    int d = (e < Ecnt) ? ei[Ecnt + e] : (e - Ecnt);
    atomicAdd(&g_deg[d], 1);
}

// single-block inclusive->exclusive scan of g_deg into g_rowstart
__global__ void k_scan() {
    __shared__ int sh[1024];
    __shared__ int carry;
    int tid = threadIdx.x;
    if (tid == 0) carry = 0;
    __syncthreads();
    for (int base = 0; base < Nn; base += 1024) {
        int i = base + tid;
        int v = (i < Nn) ? g_deg[i] : 0;
        sh[tid] = v;
        __syncthreads();
        for (int off = 1; off < 1024; off <<= 1) {
            int t = (tid >= off) ? sh[tid - off] : 0;
            __syncthreads();
            sh[tid] += t;
            __syncthreads();
        }
        if (i < Nn) g_rowstart[i] = carry + sh[tid] - v;
        __syncthreads();
        if (tid == 1023) carry += sh[1023];
        __syncthreads();
    }
    if (tid == 0) g_rowstart[Nn] = carry;
}

__global__ void k_fill(const int* __restrict__ ei) {
    int e = blockIdx.x * blockDim.x + threadIdx.x;
    if (e >= ET) return;
    int s, d;
    if (e < Ecnt) { s = ei[e]; d = ei[Ecnt + e]; }
    else          { s = d = e - Ecnt; }
    int pos = atomicAdd(&g_cursor[d], 1);
    g_csr[g_rowstart[d] + pos] = s;
}

// ---------------- GEMM: XP = X @ W  (XP always -> g_xp) ----------------
// 128 threads/block; W fully resident in smem; 32-row x tiles.
// cg = col group (float4 of output cols), rg = warp id -> rows, warp-uniform x broadcasts.
template <int K, int NCOL, int RPT, bool IN_H>
__global__ void k_gemm(const float* __restrict__ Xext, const float* __restrict__ W, int ntiles) {
    constexpr int CG = NCOL / 4;
    constexpr int RG = 128 / CG;
    constexpr int ROWS = RG * RPT;
    extern __shared__ float sm[];
    float* Ws = sm;                 // K * NCOL
    float* Xs = sm + K * NCOL;      // ROWS * K
    const float* X = IN_H ? (const float*)g_h : Xext;
    float* XP = (float*)g_xp;

    int t = threadIdx.x;
    for (int i = t; i < K * NCOL / 4; i += 128)
        ((float4*)Ws)[i] = ((const float4*)W)[i];

    int cg = t % CG;
    int rg = t / CG;

    for (int tile = blockIdx.x; tile < ntiles; tile += gridDim.x) {
        __syncthreads();   // protects Ws on first pass, Xs on later passes
        const float4* Xg = (const float4*)(X + (size_t)tile * ROWS * K);
        for (int i = t; i < ROWS * K / 4; i += 128)
            ((float4*)Xs)[i] = Xg[i];
        __syncthreads();

        float4 acc[RPT];
#pragma unroll
        for (int j = 0; j < RPT; j++) acc[j] = make_float4(0.f, 0.f, 0.f, 0.f);

        for (int k4 = 0; k4 < K / 4; k4++) {
            float xb[RPT][4];
#pragma unroll
            for (int j = 0; j < RPT; j++) {
                float4 tmp = *(const float4*)&Xs[(rg * RPT + j) * K + k4 * 4];
                xb[j][0] = tmp.x; xb[j][1] = tmp.y; xb[j][2] = tmp.z; xb[j][3] = tmp.w;
            }
#pragma unroll
            for (int kk = 0; kk < 4; kk++) {
                float4 wv = ((const float4*)Ws)[(k4 * 4 + kk) * CG + cg];
#pragma unroll
                for (int j = 0; j < RPT; j++) {
                    acc[j].x = fmaf(wv.x, xb[j][kk], acc[j].x);
                    acc[j].y = fmaf(wv.y, xb[j][kk], acc[j].y);
                    acc[j].z = fmaf(wv.z, xb[j][kk], acc[j].z);
                    acc[j].w = fmaf(wv.w, xb[j][kk], acc[j].w);
                }
            }
        }

        float4* Og = (float4*)(XP + (size_t)tile * ROWS * NCOL);
#pragma unroll
        for (int j = 0; j < RPT; j++)
            Og[(rg * RPT + j) * CG + cg] = acc[j];
    }
}

// ---------------- attention scalar terms ----------------
// conv1: asrc[n,h] = sum_c xp[n,h,c]*att_src[h,c]   (warp per node, 8-lane head reduce)
__global__ void k_att1(const float* __restrict__ att_src, const float* __restrict__ att_dst) {
    int w = (blockIdx.x * blockDim.x + threadIdx.x) >> 5;
    if (w >= Nn) return;
    int lane = threadIdx.x & 31;
    float4 xv = g_xp[w * 32 + lane];
    float4 as = ((const float4*)att_src)[lane];
    float4 ad = ((const float4*)att_dst)[lane];
    float ts = xv.x * as.x + xv.y * as.y + xv.z * as.z + xv.w * as.w;
    float td = xv.x * ad.x + xv.y * ad.y + xv.z * ad.z + xv.w * ad.w;
#pragma unroll
    for (int off = 4; off; off >>= 1) {
        ts += __shfl_down_sync(0xffffffffu, ts, off, 8);
        td += __shfl_down_sync(0xffffffffu, td, off, 8);
    }
    if ((lane & 7) == 0) {
        int h = lane >> 3;
        g_asrc[w * 4 + h] = ts;
        g_adst[w * 4 + h] = td;
    }
}

// conv2 (1 head, 64 ch): full-warp reduce of float2 per lane
__global__ void k_att2(const float* __restrict__ att_src, const float* __restrict__ att_dst) {
    int w = (blockIdx.x * blockDim.x + threadIdx.x) >> 5;
    if (w >= Nn) return;
    int lane = threadIdx.x & 31;
    float2 xv = ((const float2*)g_xp)[w * 32 + lane];
    float2 as = ((const float2*)att_src)[lane];
    float2 ad = ((const float2*)att_dst)[lane];
    float ts = xv.x * as.x + xv.y * as.y;
    float td = xv.x * ad.x + xv.y * ad.y;
#pragma unroll
    for (int off = 16; off; off >>= 1) {
        ts += __shfl_down_sync(0xffffffffu, ts, off);
        td += __shfl_down_sync(0xffffffffu, td, off);
    }
    if (lane == 0) { g_asrc[w] = ts; g_adst[w] = td; }
}

// ---------------- fused edge softmax + aggregation + epilogue (gather, no atomics) ----------------
// conv1: warp per dst; lane owns 4 cols (head = lane>>3). Writes relu(out+bias) into g_h at col_off.
__global__ void k_gather1(const float* __restrict__ bias, int col_off) {
    int d = (blockIdx.x * blockDim.x + threadIdx.x) >> 5;
    if (d >= Nn) return;
    int lane = threadIdx.x & 31;
    int h = lane >> 3;
    float ad = g_adst[d * 4 + h];
    int beg = g_rowstart[d], end = g_rowstart[d + 1];
    float4 acc = make_float4(0.f, 0.f, 0.f, 0.f);
    float dsum = 0.f;
    for (int j = beg; j < end; j++) {
        int s = g_csr[j];
        float a = g_asrc[s * 4 + h] + ad;
        a = (a > 0.f) ? a : 0.2f * a;
        float wgt = __expf(a);
        float4 xv = g_xp[s * 32 + lane];
        acc.x = fmaf(wgt, xv.x, acc.x);
        acc.y = fmaf(wgt, xv.y, acc.y);
        acc.z = fmaf(wgt, xv.z, acc.z);
        acc.w = fmaf(wgt, xv.w, acc.w);
        dsum += wgt;
    }
    float inv = 1.0f / dsum;   // self-loop guarantees dsum > 0
    float4 b = ((const float4*)bias)[lane];
    float4 o;
    o.x = fmaxf(fmaf(acc.x, inv, b.x), 0.f);
    o.y = fmaxf(fmaf(acc.y, inv, b.y), 0.f);
    o.z = fmaxf(fmaf(acc.z, inv, b.z), 0.f);
    o.w = fmaxf(fmaf(acc.w, inv, b.w), 0.f);
    float* hrow = (float*)g_h + (size_t)d * 256 + col_off;
    ((float4*)hrow)[lane] = o;
}

// conv2: 1 head, 64 output cols (float2 per lane). Writes final output (+bias, no relu).
__global__ void k_gather2(const float* __restrict__ bias, float* __restrict__ out) {
    int d = (blockIdx.x * blockDim.x + threadIdx.x) >> 5;
    if (d >= Nn) return;
    int lane = threadIdx.x & 31;
    float ad = g_adst[d];
    int beg = g_rowstart[d], end = g_rowstart[d + 1];
    float2 acc = make_float2(0.f, 0.f);
    float dsum = 0.f;
    for (int j = beg; j < end; j++) {
        int s = g_csr[j];
        float a = g_asrc[s] + ad;
        a = (a > 0.f) ? a : 0.2f * a;
        float wgt = __expf(a);
        float2 xv = ((const float2*)g_xp)[s * 32 + lane];
        acc.x = fmaf(wgt, xv.x, acc.x);
        acc.y = fmaf(wgt, xv.y, acc.y);
        dsum += wgt;
    }
    float inv = 1.0f / dsum;
    float2 b = ((const float2*)bias)[lane];
    float2 o;
    o.x = fmaf(acc.x, inv, b.x);
    o.y = fmaf(acc.y, inv, b.y);
    ((float2*)out)[d * 32 + lane] = o;
}

// ---------------- launch ----------------
extern "C" void kernel_launch(void* const* d_in, const int* in_sizes, int n_in,
                              void* d_out, int out_size) {
    const float* x_ppi = (const float*)d_in[0];
    const float* x_go  = (const float*)d_in[1];
    const int*   ei    = (const int*)d_in[2];
    const float* W1    = (const float*)d_in[3];
    const float* as1   = (const float*)d_in[4];
    const float* ad1   = (const float*)d_in[5];
    const float* b1    = (const float*)d_in[6];
    const float* W2    = (const float*)d_in[7];
    const float* as2   = (const float*)d_in[8];
    const float* ad2   = (const float*)d_in[9];
    const float* b2    = (const float*)d_in[10];
    float* out = (float*)d_out;

    // GEMM1: K=128, NCOL=128, RPT=8 -> smem 64KB(W) + 16KB(X) = 80KB
    // GEMM2: K=256, NCOL=64,  RPT=4 -> smem 64KB(W) + 32KB(X) = 96KB
    cudaFuncSetAttribute(k_gemm<128, 128, 8, false>,
                         cudaFuncAttributeMaxDynamicSharedMemorySize, 81920);
    cudaFuncSetAttribute(k_gemm<256, 64, 4, true>,
                         cudaFuncAttributeMaxDynamicSharedMemorySize, 98304);

    const int NTILES = Nn / 32;        // 3125
    const int GEMM_GRID = 1184;        // 148 SMs * 8
    const int NODE_BLOCKS = Nn * 32 / 256;  // 12500 (warp per node)
    const int EDGE_BLOCKS = (ET + 255) / 256;

    // CSR build (shared by all three convs)
    k_zero_counts<<<(Nn + 255) / 256, 256>>>();
    k_degree<<<EDGE_BLOCKS, 256>>>(ei);
    k_scan<<<1, 1024>>>();
    k_fill<<<EDGE_BLOCKS, 256>>>(ei);

    // conv1 on x_ppi -> h[:, 0:128]
    k_gemm<128, 128, 8, false><<<GEMM_GRID, 128, 81920>>>(x_ppi, W1, NTILES);
    k_att1<<<NODE_BLOCKS, 256>>>(as1, ad1);
    k_gather1<<<NODE_BLOCKS, 256>>>(b1, 0);

    // conv1 on x_go -> h[:, 128:256]
    k_gemm<128, 128, 8, false><<<GEMM_GRID, 128, 81920>>>(x_go, W1, NTILES);
    k_att1<<<NODE_BLOCKS, 256>>>(as1, ad1);
    k_gather1<<<NODE_BLOCKS, 256>>>(b1, 128);

    // conv2 on h -> out
    k_gemm<256, 64, 4, true><<<GEMM_GRID, 128, 98304>>>(nullptr, W2, NTILES);
    k_att2<<<NODE_BLOCKS, 256>>>(as2, ad2);
    k_gather2<<<NODE_BLOCKS, 256>>>(b2, out);
}